// round 12
// baseline (speedup 1.0000x reference)
#include <cuda_runtime.h>
#include <cuda_bf16.h>
#include <math_constants.h>

#define MTILE 64

__device__ __align__(16) __nv_bfloat16 g_ws1p[24*16*32*4];
__device__ __align__(16) __nv_bfloat16 g_ws2p[ 8*16*32*4];
__device__ __align__(16) __nv_bfloat16 g_wf1p[ 2*16*32*4];
__device__ __align__(16) __nv_bfloat16 g_wf2p[ 8*16*32*4];
__device__ __align__(16) __nv_bfloat16 g_wo1p[ 8* 8*32*4];

__device__ __forceinline__ float silu_f(float a){ return a/(1.0f+__expf(-a)); }

__global__ void prep_kernel(const float* __restrict__ ws1, const float* __restrict__ ws2,
                            const float* __restrict__ wf1, const float* __restrict__ wf2,
                            const float* __restrict__ wo1,
                            float* __restrict__ rho, const float* __restrict__ fb, int n_rho)
{
    int idx = blockIdx.x*blockDim.x + threadIdx.x;
    if (idx < 736*32) {
        int g = idx >> 5, lane = idx & 31;
        const float* src; __nv_bfloat16* dst; int NT, N, gl;
        if      (g < 384) { src=ws1; dst=g_ws1p; NT=16; N=128; gl=g;     }
        else if (g < 512) { src=ws2; dst=g_ws2p; NT=16; N=128; gl=g-384; }
        else if (g < 544) { src=wf1; dst=g_wf1p; NT=16; N=128; gl=g-512; }
        else if (g < 672) { src=wf2; dst=g_wf2p; NT=16; N=128; gl=g-544; }
        else              { src=wo1; dst=g_wo1p; NT=8;  N=64;  gl=g-672; }
        int kt = gl / NT, nt = gl % NT;
        int k0 = kt*16 + (lane&3)*2;
        int n  = nt*8 + (lane>>2);
        __nv_bfloat16* o = dst + ((size_t)gl*32 + lane)*4;
        o[0] = __float2bfloat16(src[(k0+0)*N + n]);
        o[1] = __float2bfloat16(src[(k0+1)*N + n]);
        o[2] = __float2bfloat16(src[(k0+8)*N + n]);
        o[3] = __float2bfloat16(src[(k0+9)*N + n]);
    }
    int r = idx - 736*32;
    if (r >= 0 && r < n_rho) rho[r] = fb[0];
}

// 4 row-blocks (64 edges) x NTU n-tiles per warp; each B fragment feeds 4 MMAs.
template<int KT, int NTT, int NTU>
__device__ __forceinline__ void gemm4(float (*acc)[4], unsigned aBase,
                                      const uint2* __restrict__ Bq, int lane)
{
    #pragma unroll
    for (int kt = 0; kt < KT; kt++){
        unsigned a[4][4];
        #pragma unroll
        for (int rb = 0; rb < 4; rb++)
            asm volatile("ldmatrix.sync.aligned.m8n8.x4.shared.b16 {%0,%1,%2,%3}, [%4];"
                : "=r"(a[rb][0]),"=r"(a[rb][1]),"=r"(a[rb][2]),"=r"(a[rb][3])
                : "r"(aBase + rb*16*272 + kt*32));
        #pragma unroll
        for (int nt = 0; nt < NTU; nt++){
            uint2 b = __ldg(&Bq[(kt*NTT+nt)*32 + lane]);
            #pragma unroll
            for (int rb = 0; rb < 4; rb++)
                asm volatile("mma.sync.aligned.m16n8k16.row.col.f32.bf16.bf16.f32 "
                    "{%0,%1,%2,%3}, {%4,%5,%6,%7}, {%8,%9}, {%0,%1,%2,%3};"
                    : "+f"(acc[rb*NTU+nt][0]),"+f"(acc[rb*NTU+nt][1]),
                      "+f"(acc[rb*NTU+nt][2]),"+f"(acc[rb*NTU+nt][3])
                    : "r"(a[rb][0]),"r"(a[rb][1]),"r"(a[rb][2]),"r"(a[rb][3]),
                      "r"(b.x), "r"(b.y));
        }
    }
}

#define OFF_A 0
#define OFF_B 17408
#define OFF_W 34816
#define OFF_SC 52224
// dist(256) env(256) rhat(768) pidx(256) aidx(256) = 1792; lnp float2[4][64] @+1792 (2048)
#define SMEM_BYTES 56064

__global__ void __launch_bounds__(128, 4) cfr_mma_kernel(
    const float* __restrict__ diff, const float* __restrict__ S, const float* __restrict__ V,
    const int* __restrict__ aidx, const int* __restrict__ pidx,
    const float* __restrict__ b_s1, const float* __restrict__ g_ln, const float* __restrict__ b_ln,
    const float* __restrict__ b_s2, const float* __restrict__ b_f1, const float* __restrict__ b_f2,
    const float* __restrict__ b_o1, const float* __restrict__ w_o2, const float* __restrict__ b_o2,
    float* __restrict__ rho, int E)
{
    extern __shared__ char sm[];
    __nv_bfloat16* bufA = (__nv_bfloat16*)(sm + OFF_A);
    __nv_bfloat16* bufB = (__nv_bfloat16*)(sm + OFF_B);
    __nv_bfloat16* bufW = (__nv_bfloat16*)(sm + OFF_W);
    float*  sh_dist = (float*)(sm + OFF_SC);
    float*  sh_env  = (float*)(sm + OFF_SC + 256);
    float*  sh_rhat = (float*)(sm + OFF_SC + 512);
    int*    sh_pidx = (int*)  (sm + OFF_SC + 1280);
    int*    sh_aidx = (int*)  (sm + OFF_SC + 1536);
    float2* sh_lnp  = (float2*)(sm + OFF_SC + 1792);
    float*  sh_m    = (float*)(sm + OFF_SC + 1792);   // reused after LN

    const int tid  = threadIdx.x;
    const int lane = tid & 31;
    const int w    = tid >> 5;      // warp 0..3 owns cols w*32..w*32+31
    const int j0   = w * 16;        // warp's gather slice (16 edges)
    const int e0   = blockIdx.x * MTILE;

    // ---- per-edge scalars (warp's 16 edges) ----
    if (lane < 16) {
        int j = j0 + lane;
        int e = e0 + j;
        float dx = 0.f, dy = 0.f, dz = 1e-3f;
        int ai = 0, pi = 0;
        if (e < E) { dx = diff[3*e]; dy = diff[3*e+1]; dz = diff[3*e+2]; ai = aidx[e]; pi = pidx[e]; }
        float sq   = dx*dx + dy*dy + dz*dz;
        float dist = sqrtf(sq);
        float inv  = rsqrtf(sq + 1e-8f);
        sh_rhat[j*3+0] = dx*inv;
        sh_rhat[j*3+1] = dy*inv;
        sh_rhat[j*3+2] = dz*inv;
        sh_dist[j] = dist;
        float x  = dist * 0.25f;
        float x2 = x*x, x5 = x2*x2*x;
        float env = 1.0f - 21.0f*x5 + 35.0f*x5*x - 15.0f*x5*x2;
        sh_env[j]  = (dist < 4.0f) ? env : 0.0f;
        sh_pidx[j] = pi;
        sh_aidx[j] = ai;
    }
    __syncwarp();

    // ---- sinc RBF -> bufW cols 0..31 (warp's 16 edges, lane = n) ----
    {
        const float c  = CUDART_PI_F * 0.25f;
        const float nn = (float)(lane + 1);
        #pragma unroll
        for (int j = 0; j < 16; j++){
            int row = j0 + j;
            float d = sh_dist[row];
            bufW[row*136 + lane] = __float2bfloat16(__sinf(d * nn * c) / d);
        }
    }
    __syncthreads();   // (1)

    const unsigned uBase = (unsigned)__cvta_generic_to_shared(sm);
    const unsigned uRow  = (lane&15)*272 + ((lane>>4)<<4);
    const unsigned uA = uBase + OFF_A + uRow;
    const unsigned uB = uBase + OFF_B + uRow;
    const unsigned uW = uBase + OFF_W + uRow;

    const int q2 = (lane & 3) * 2;
    const int r0 = lane >> 2;            // epilogue rows: r0 + 8*i, i=0..7
    const int nb = w * 32;

    float acc[16][4];

    // ================= filter branch =================
    #pragma unroll
    for (int i = 0; i < 16; i++){ acc[i][0]=acc[i][1]=acc[i][2]=acc[i][3]=0.f; }
    gemm4<2,16,4>(acc, uW, (const uint2*)g_wf1p + w*128, lane);
    #pragma unroll
    for (int rb = 0; rb < 4; rb++)
    #pragma unroll
    for (int nt = 0; nt < 4; nt++){
        int c0 = nb + nt*8 + q2;
        float2 bb = *(const float2*)(b_f1 + c0);
        float* a = acc[rb*4+nt];
        *(__nv_bfloat162*)(bufA + (r0+rb*16)*136 + c0) =
            __floats2bfloat162_rn(silu_f(a[0]+bb.x), silu_f(a[1]+bb.y));
        *(__nv_bfloat162*)(bufA + (r0+rb*16+8)*136 + c0) =
            __floats2bfloat162_rn(silu_f(a[2]+bb.x), silu_f(a[3]+bb.y));
    }
    __syncthreads();   // (2)

    #pragma unroll
    for (int i = 0; i < 16; i++){ acc[i][0]=acc[i][1]=acc[i][2]=acc[i][3]=0.f; }
    gemm4<8,16,4>(acc, uA, (const uint2*)g_wf2p + w*128, lane);
    #pragma unroll
    for (int rb = 0; rb < 4; rb++)
    #pragma unroll
    for (int nt = 0; nt < 4; nt++){
        int c0 = nb + nt*8 + q2;
        float2 bb = *(const float2*)(b_f2 + c0);
        float* a = acc[rb*4+nt];
        *(__nv_bfloat162*)(bufW + (r0+rb*16)*136 + c0) = __floats2bfloat162_rn(a[0]+bb.x, a[1]+bb.y);
        *(__nv_bfloat162*)(bufW + (r0+rb*16+8)*136 + c0) = __floats2bfloat162_rn(a[2]+bb.x, a[3]+bb.y);
    }
    // bufW re-read only by this warp at same coords -> no barrier

    // ---- gather S -> bufB ----
    #pragma unroll 4
    for (int j = 0; j < 16; j++){
        int row = j0 + j;
        int a = sh_aidx[row];
        float4 s4 = __ldg((const float4*)(S + (size_t)a * 128) + lane);
        *(__nv_bfloat162*)(bufB + row*136 + lane*4)     = __floats2bfloat162_rn(s4.x, s4.y);
        *(__nv_bfloat162*)(bufB + row*136 + lane*4 + 2) = __floats2bfloat162_rn(s4.z, s4.w);
    }
    __syncthreads();   // (3) bufB ready; also all f2 reads of bufA done
    #pragma unroll
    for (int i = 0; i < 16; i++){ acc[i][0]=acc[i][1]=acc[i][2]=acc[i][3]=0.f; }
    gemm4<8,16,4>(acc, uB, (const uint2*)g_ws1p + w*128, lane);
    __syncthreads();   // (4) all s1a reads of bufB done

    // ---- gather V -> n_e in bufB, q_pi in bufA ----
    #pragma unroll 2
    for (int j = 0; j < 16; j++){
        int row = j0 + j;
        int a = sh_aidx[row];
        float rx = sh_rhat[row*3+0];
        float ry = sh_rhat[row*3+1];
        float rz = sh_rhat[row*3+2];
        const float4* Vp = (const float4*)(V + (size_t)a * 384);
        float4 v0 = __ldg(Vp + lane);
        float4 v1 = __ldg(Vp + 32 + lane);
        float4 v2 = __ldg(Vp + 64 + lane);
        float n0 = sqrtf(v0.x*v0.x + v1.x*v1.x + v2.x*v2.x + 1e-8f);
        float n1 = sqrtf(v0.y*v0.y + v1.y*v1.y + v2.y*v2.y + 1e-8f);
        float n2 = sqrtf(v0.z*v0.z + v1.z*v1.z + v2.z*v2.z + 1e-8f);
        float n3 = sqrtf(v0.w*v0.w + v1.w*v1.w + v2.w*v2.w + 1e-8f);
        float q0 = v0.x*rx + v1.x*ry + v2.x*rz;
        float q1 = v0.y*rx + v1.y*ry + v2.y*rz;
        float q2v= v0.z*rx + v1.z*ry + v2.z*rz;
        float q3 = v0.w*rx + v1.w*ry + v2.w*rz;
        *(__nv_bfloat162*)(bufB + row*136 + lane*4)     = __floats2bfloat162_rn(n0, n1);
        *(__nv_bfloat162*)(bufB + row*136 + lane*4 + 2) = __floats2bfloat162_rn(n2, n3);
        *(__nv_bfloat162*)(bufA + row*136 + lane*4)     = __floats2bfloat162_rn(q0, q1);
        *(__nv_bfloat162*)(bufA + row*136 + lane*4 + 2) = __floats2bfloat162_rn(q2v, q3);
    }
    __syncthreads();   // (5)
    gemm4<8,16,4>(acc, uB, (const uint2*)g_ws1p + 4096 + w*128, lane);
    gemm4<8,16,4>(acc, uA, (const uint2*)g_ws1p + 8192 + w*128, lane);

    // ---- LayerNorm: bias + partials over warp's 32 cols, 4-way combine ----
    float sv[8] = {0,0,0,0,0,0,0,0}, qv[8] = {0,0,0,0,0,0,0,0};  // rows r0+8i
    #pragma unroll
    for (int rb = 0; rb < 4; rb++)
    #pragma unroll
    for (int nt = 0; nt < 4; nt++){
        int c0 = nb + nt*8 + q2;
        float2 bb = *(const float2*)(b_s1 + c0);
        float* a = acc[rb*4+nt];
        a[0]+=bb.x; a[1]+=bb.y; a[2]+=bb.x; a[3]+=bb.y;
        sv[2*rb]   += a[0]+a[1];  qv[2*rb]   += a[0]*a[0]+a[1]*a[1];
        sv[2*rb+1] += a[2]+a[3];  qv[2*rb+1] += a[2]*a[2]+a[3]*a[3];
    }
    #pragma unroll
    for (int o = 1; o < 4; o <<= 1)
    #pragma unroll
    for (int i = 0; i < 8; i++){
        sv[i] += __shfl_xor_sync(0xffffffffu, sv[i], o);
        qv[i] += __shfl_xor_sync(0xffffffffu, qv[i], o);
    }
    if ((lane & 3) == 0){
        #pragma unroll
        for (int i = 0; i < 8; i++){
            int row = r0 + ((i&1)*8) + (i>>1)*16;
            sh_lnp[w*64 + row] = make_float2(sv[i], qv[i]);
        }
    }
    __syncthreads();   // (6) partials staged (also: all s1 reads done)
    #pragma unroll
    for (int rb = 0; rb < 4; rb++){
        float mu[2], rs[2];
        #pragma unroll
        for (int h = 0; h < 2; h++){
            int row = r0 + rb*16 + h*8;
            float ss = 0.f, qq = 0.f;
            #pragma unroll
            for (int ww = 0; ww < 4; ww++){
                float2 p = sh_lnp[ww*64 + row];
                ss += p.x; qq += p.y;
            }
            mu[h] = ss*(1.f/128.f);
            rs[h] = rsqrtf(qq*(1.f/128.f) - mu[h]*mu[h] + 1e-5f);
        }
        #pragma unroll
        for (int nt = 0; nt < 4; nt++){
            int c0 = nb + nt*8 + q2;
            float2 gg = *(const float2*)(g_ln + c0);
            float2 bl = *(const float2*)(b_ln + c0);
            float* a = acc[rb*4+nt];
            float v0 = silu_f((a[0]-mu[0])*rs[0]*gg.x + bl.x);
            float v1 = silu_f((a[1]-mu[0])*rs[0]*gg.y + bl.y);
            float v2 = silu_f((a[2]-mu[1])*rs[1]*gg.x + bl.x);
            float v3 = silu_f((a[3]-mu[1])*rs[1]*gg.y + bl.y);
            *(__nv_bfloat162*)(bufA + (r0+rb*16)*136 + c0)   = __floats2bfloat162_rn(v0, v1);
            *(__nv_bfloat162*)(bufA + (r0+rb*16+8)*136 + c0) = __floats2bfloat162_rn(v2, v3);
        }
    }
    __syncthreads();   // (7)

    // ---- state L2 + fuse z = W*state -> bufB ----
    #pragma unroll
    for (int i = 0; i < 16; i++){ acc[i][0]=acc[i][1]=acc[i][2]=acc[i][3]=0.f; }
    gemm4<8,16,4>(acc, uA, (const uint2*)g_ws2p + w*128, lane);
    #pragma unroll
    for (int rb = 0; rb < 4; rb++)
    #pragma unroll
    for (int nt = 0; nt < 4; nt++){
        int c0 = nb + nt*8 + q2;
        float2 bb  = *(const float2*)(b_s2 + c0);
        float2 wlo = __bfloat1622float2(*(__nv_bfloat162*)(bufW + (r0+rb*16)*136 + c0));
        float2 whi = __bfloat1622float2(*(__nv_bfloat162*)(bufW + (r0+rb*16+8)*136 + c0));
        float* a = acc[rb*4+nt];
        *(__nv_bfloat162*)(bufB + (r0+rb*16)*136 + c0) =
            __floats2bfloat162_rn((a[0]+bb.x)*wlo.x, (a[1]+bb.y)*wlo.y);
        *(__nv_bfloat162*)(bufB + (r0+rb*16+8)*136 + c0) =
            __floats2bfloat162_rn((a[2]+bb.x)*whi.x, (a[3]+bb.y)*whi.y);
    }
    __syncthreads();   // (8)

    // ---- output head: z @ w_o1 (warp covers 16 of 64 cols) ----
    #pragma unroll
    for (int i = 0; i < 8; i++){ acc[i][0]=acc[i][1]=acc[i][2]=acc[i][3]=0.f; }
    gemm4<8,8,2>(acc, uB, (const uint2*)g_wo1p + w*64, lane);
    float m[8] = {0,0,0,0,0,0,0,0};
    #pragma unroll
    for (int rb = 0; rb < 4; rb++)
    #pragma unroll
    for (int nt = 0; nt < 2; nt++){
        int c0 = w*16 + nt*8 + q2;
        float2 bb = *(const float2*)(b_o1 + c0);
        float2 w2 = *(const float2*)(w_o2 + c0);
        float* a = acc[rb*2+nt];
        m[2*rb]   += silu_f(a[0]+bb.x)*w2.x + silu_f(a[1]+bb.y)*w2.y;
        m[2*rb+1] += silu_f(a[2]+bb.x)*w2.x + silu_f(a[3]+bb.y)*w2.y;
    }
    #pragma unroll
    for (int i = 0; i < 8; i++){
        m[i] += __shfl_xor_sync(0xffffffffu, m[i], 1);
        m[i] += __shfl_xor_sync(0xffffffffu, m[i], 2);
    }
    if ((lane & 3) == 0){
        #pragma unroll
        for (int i = 0; i < 8; i++){
            int row = r0 + ((i&1)*8) + (i>>1)*16;
            sh_m[w*64 + row] = m[i];
        }
    }
    __syncthreads();   // (9)
    if (tid < MTILE){
        int e = e0 + tid;
        if (e < E){
            float ms = sh_m[tid] + sh_m[64+tid] + sh_m[128+tid] + sh_m[192+tid] + b_o2[0];
            atomicAdd(rho + sh_pidx[tid], ms * sh_env[tid]);
        }
    }
}

extern "C" void kernel_launch(void* const* d_in, const int* in_sizes, int n_in,
                              void* d_out, int out_size)
{
    const float* diff = (const float*)d_in[0];
    const float* S    = (const float*)d_in[1];
    const float* V    = (const float*)d_in[2];
    const int*   aidx = (const int*)d_in[3];
    const int*   pidx = (const int*)d_in[4];

    int base = 5;
    if (n_in > 5 && in_sizes[5] == 1) base = 6;

    const float* w_s1 = (const float*)d_in[base + 0];
    const float* b_s1 = (const float*)d_in[base + 1];
    const float* g_ln = (const float*)d_in[base + 2];
    const float* b_ln = (const float*)d_in[base + 3];
    const float* w_s2 = (const float*)d_in[base + 4];
    const float* b_s2 = (const float*)d_in[base + 5];
    const float* w_f1 = (const float*)d_in[base + 6];
    const float* b_f1 = (const float*)d_in[base + 7];
    const float* w_f2 = (const float*)d_in[base + 8];
    const float* b_f2 = (const float*)d_in[base + 9];
    const float* w_o1 = (const float*)d_in[base + 10];
    const float* b_o1 = (const float*)d_in[base + 11];
    const float* w_o2 = (const float*)d_in[base + 12];
    const float* b_o2 = (const float*)d_in[base + 13];
    const float* fb   = (const float*)d_in[base + 14];

    int E = in_sizes[0] / 3;
    float* rho = (float*)d_out;

    int prep_threads = 736*32 + out_size;
    prep_kernel<<<(prep_threads + 255)/256, 256>>>(w_s1, w_s2, w_f1, w_f2, w_o1,
                                                   rho, fb, out_size);

    cudaFuncSetAttribute(cfr_mma_kernel, cudaFuncAttributeMaxDynamicSharedMemorySize, SMEM_BYTES);
    cfr_mma_kernel<<<(E + MTILE - 1)/MTILE, 128, SMEM_BYTES>>>(
        diff, S, V, aidx, pidx,
        b_s1, g_ln, b_ln, b_s2, b_f1, b_f2,
        b_o1, w_o2, b_o2, rho, E);
}

// round 13
// speedup vs baseline: 1.0197x; 1.0197x over previous
#include <cuda_runtime.h>
#include <cuda_bf16.h>
#include <math_constants.h>

#define MTILE 64
#define THREADS 256

__device__ __align__(16) __nv_bfloat16 g_ws1p[24*16*32*4];
__device__ __align__(16) __nv_bfloat16 g_ws2p[ 8*16*32*4];
__device__ __align__(16) __nv_bfloat16 g_wf1p[ 2*16*32*4];
__device__ __align__(16) __nv_bfloat16 g_wf2p[ 8*16*32*4];
__device__ __align__(16) __nv_bfloat16 g_wo1p[ 8* 8*32*4];

__device__ __forceinline__ float silu_f(float a){ return a/(1.0f+__expf(-a)); }

__global__ void prep_kernel(const float* __restrict__ ws1, const float* __restrict__ ws2,
                            const float* __restrict__ wf1, const float* __restrict__ wf2,
                            const float* __restrict__ wo1,
                            float* __restrict__ rho, const float* __restrict__ fb, int n_rho)
{
    int idx = blockIdx.x*blockDim.x + threadIdx.x;
    if (idx < 736*32) {
        int g = idx >> 5, lane = idx & 31;
        const float* src; __nv_bfloat16* dst; int NT, N, gl;
        if      (g < 384) { src=ws1; dst=g_ws1p; NT=16; N=128; gl=g;     }
        else if (g < 512) { src=ws2; dst=g_ws2p; NT=16; N=128; gl=g-384; }
        else if (g < 544) { src=wf1; dst=g_wf1p; NT=16; N=128; gl=g-512; }
        else if (g < 672) { src=wf2; dst=g_wf2p; NT=16; N=128; gl=g-544; }
        else              { src=wo1; dst=g_wo1p; NT=8;  N=64;  gl=g-672; }
        int kt = gl / NT, nt = gl % NT;
        int k0 = kt*16 + (lane&3)*2;
        int n  = nt*8 + (lane>>2);
        __nv_bfloat16* o = dst + ((size_t)gl*32 + lane)*4;
        o[0] = __float2bfloat16(src[(k0+0)*N + n]);
        o[1] = __float2bfloat16(src[(k0+1)*N + n]);
        o[2] = __float2bfloat16(src[(k0+8)*N + n]);
        o[3] = __float2bfloat16(src[(k0+9)*N + n]);
    }
    int r = idx - 736*32;
    if (r >= 0 && r < n_rho) rho[r] = fb[0];
}

// 4 row-blocks (64 edges) x NTU n-tiles per warp; each B fragment feeds 4 MMAs.
template<int KT, int NTT, int NTU>
__device__ __forceinline__ void gemm4(float (*acc)[4], unsigned aBase,
                                      const uint2* __restrict__ Bq, int lane)
{
    #pragma unroll
    for (int kt = 0; kt < KT; kt++){
        unsigned a[4][4];
        #pragma unroll
        for (int rb = 0; rb < 4; rb++)
            asm volatile("ldmatrix.sync.aligned.m8n8.x4.shared.b16 {%0,%1,%2,%3}, [%4];"
                : "=r"(a[rb][0]),"=r"(a[rb][1]),"=r"(a[rb][2]),"=r"(a[rb][3])
                : "r"(aBase + rb*16*272 + kt*32));
        #pragma unroll
        for (int nt = 0; nt < NTU; nt++){
            uint2 b = __ldg(&Bq[(kt*NTT+nt)*32 + lane]);
            #pragma unroll
            for (int rb = 0; rb < 4; rb++)
                asm volatile("mma.sync.aligned.m16n8k16.row.col.f32.bf16.bf16.f32 "
                    "{%0,%1,%2,%3}, {%4,%5,%6,%7}, {%8,%9}, {%0,%1,%2,%3};"
                    : "+f"(acc[rb*NTU+nt][0]),"+f"(acc[rb*NTU+nt][1]),
                      "+f"(acc[rb*NTU+nt][2]),"+f"(acc[rb*NTU+nt][3])
                    : "r"(a[rb][0]),"r"(a[rb][1]),"r"(a[rb][2]),"r"(a[rb][3]),
                      "r"(b.x), "r"(b.y));
        }
    }
}

#define OFF_A 0
#define OFF_B 17408
#define OFF_W 34816
#define OFF_SC 52224
// dist(256) env(256) rhat(768) pidx(256) aidx(256) = 1792; lnp float2[8][64] @+1792 (4096)
#define SMEM_BYTES 58112

__global__ void __launch_bounds__(THREADS, 3) cfr_mma_kernel(
    const float* __restrict__ diff, const float* __restrict__ S, const float* __restrict__ V,
    const int* __restrict__ aidx, const int* __restrict__ pidx,
    const float* __restrict__ b_s1, const float* __restrict__ g_ln, const float* __restrict__ b_ln,
    const float* __restrict__ b_s2, const float* __restrict__ b_f1, const float* __restrict__ b_f2,
    const float* __restrict__ b_o1, const float* __restrict__ w_o2, const float* __restrict__ b_o2,
    float* __restrict__ rho, int E)
{
    extern __shared__ char sm[];
    __nv_bfloat16* bufA = (__nv_bfloat16*)(sm + OFF_A);
    __nv_bfloat16* bufB = (__nv_bfloat16*)(sm + OFF_B);
    __nv_bfloat16* bufW = (__nv_bfloat16*)(sm + OFF_W);
    float*  sh_dist = (float*)(sm + OFF_SC);
    float*  sh_env  = (float*)(sm + OFF_SC + 256);
    float*  sh_rhat = (float*)(sm + OFF_SC + 512);
    int*    sh_pidx = (int*)  (sm + OFF_SC + 1280);
    int*    sh_aidx = (int*)  (sm + OFF_SC + 1536);
    float2* sh_lnp  = (float2*)(sm + OFF_SC + 1792);
    float*  sh_m    = (float*)(sm + OFF_SC + 1792);   // reused after LN

    const int tid  = threadIdx.x;
    const int lane = tid & 31;
    const int w    = tid >> 5;      // warp 0..7 owns cols w*16..w*16+15
    const int j0   = w * 8;         // warp's gather slice (8 edges)
    const int e0   = blockIdx.x * MTILE;

    // ---- per-edge scalars (warp's 8 edges, lanes 0-7) ----
    if (lane < 8) {
        int j = j0 + lane;
        int e = e0 + j;
        float dx = 0.f, dy = 0.f, dz = 1e-3f;
        int ai = 0, pi = 0;
        if (e < E) { dx = diff[3*e]; dy = diff[3*e+1]; dz = diff[3*e+2]; ai = aidx[e]; pi = pidx[e]; }
        float sq   = dx*dx + dy*dy + dz*dz;
        float dist = sqrtf(sq);
        float inv  = rsqrtf(sq + 1e-8f);
        sh_rhat[j*3+0] = dx*inv;
        sh_rhat[j*3+1] = dy*inv;
        sh_rhat[j*3+2] = dz*inv;
        sh_dist[j] = dist;
        float x  = dist * 0.25f;
        float x2 = x*x, x5 = x2*x2*x;
        float env = 1.0f - 21.0f*x5 + 35.0f*x5*x - 15.0f*x5*x2;
        sh_env[j]  = (dist < 4.0f) ? env : 0.0f;
        sh_pidx[j] = pi;
        sh_aidx[j] = ai;
    }
    __syncwarp();

    // ---- sinc RBF -> bufW cols 0..31 (warp's 8 edges, lane = n) ----
    {
        const float c  = CUDART_PI_F * 0.25f;
        const float nn = (float)(lane + 1);
        #pragma unroll
        for (int j = 0; j < 8; j++){
            int row = j0 + j;
            float d = sh_dist[row];
            bufW[row*136 + lane] = __float2bfloat16(__sinf(d * nn * c) / d);
        }
    }
    __syncthreads();   // (1)

    const unsigned uBase = (unsigned)__cvta_generic_to_shared(sm);
    const unsigned uRow  = (lane&15)*272 + ((lane>>4)<<4);
    const unsigned uA = uBase + OFF_A + uRow;
    const unsigned uB = uBase + OFF_B + uRow;
    const unsigned uW = uBase + OFF_W + uRow;

    const int q2 = (lane & 3) * 2;
    const int r0 = lane >> 2;            // epilogue rows: r0 + 8*i
    const int nb = w * 16;

    float acc[8][4];

    // ================= filter branch =================
    #pragma unroll
    for (int i = 0; i < 8; i++){ acc[i][0]=acc[i][1]=acc[i][2]=acc[i][3]=0.f; }
    gemm4<2,16,2>(acc, uW, (const uint2*)g_wf1p + w*64, lane);
    #pragma unroll
    for (int rb = 0; rb < 4; rb++)
    #pragma unroll
    for (int nt = 0; nt < 2; nt++){
        int c0 = nb + nt*8 + q2;
        float2 bb = *(const float2*)(b_f1 + c0);
        float* a = acc[rb*2+nt];
        *(__nv_bfloat162*)(bufA + (r0+rb*16)*136 + c0) =
            __floats2bfloat162_rn(silu_f(a[0]+bb.x), silu_f(a[1]+bb.y));
        *(__nv_bfloat162*)(bufA + (r0+rb*16+8)*136 + c0) =
            __floats2bfloat162_rn(silu_f(a[2]+bb.x), silu_f(a[3]+bb.y));
    }
    __syncthreads();   // (2)

    #pragma unroll
    for (int i = 0; i < 8; i++){ acc[i][0]=acc[i][1]=acc[i][2]=acc[i][3]=0.f; }
    gemm4<8,16,2>(acc, uA, (const uint2*)g_wf2p + w*64, lane);
    #pragma unroll
    for (int rb = 0; rb < 4; rb++)
    #pragma unroll
    for (int nt = 0; nt < 2; nt++){
        int c0 = nb + nt*8 + q2;
        float2 bb = *(const float2*)(b_f2 + c0);
        float* a = acc[rb*2+nt];
        *(__nv_bfloat162*)(bufW + (r0+rb*16)*136 + c0) = __floats2bfloat162_rn(a[0]+bb.x, a[1]+bb.y);
        *(__nv_bfloat162*)(bufW + (r0+rb*16+8)*136 + c0) = __floats2bfloat162_rn(a[2]+bb.x, a[3]+bb.y);
    }
    // bufW re-read only by this warp at same coords -> no barrier

    // ---- gather S -> bufB (warp's 8 edges) ----
    #pragma unroll 4
    for (int j = 0; j < 8; j++){
        int row = j0 + j;
        int a = sh_aidx[row];
        float4 s4 = __ldg((const float4*)(S + (size_t)a * 128) + lane);
        *(__nv_bfloat162*)(bufB + row*136 + lane*4)     = __floats2bfloat162_rn(s4.x, s4.y);
        *(__nv_bfloat162*)(bufB + row*136 + lane*4 + 2) = __floats2bfloat162_rn(s4.z, s4.w);
    }
    __syncthreads();   // (3) bufB ready; all f2 reads of bufA done
    #pragma unroll
    for (int i = 0; i < 8; i++){ acc[i][0]=acc[i][1]=acc[i][2]=acc[i][3]=0.f; }
    gemm4<8,16,2>(acc, uB, (const uint2*)g_ws1p + w*64, lane);
    __syncthreads();   // (4) all s1a reads of bufB done

    // ---- gather V -> n_e in bufB, q_pi in bufA (warp's 8 edges) ----
    #pragma unroll 2
    for (int j = 0; j < 8; j++){
        int row = j0 + j;
        int a = sh_aidx[row];
        float rx = sh_rhat[row*3+0];
        float ry = sh_rhat[row*3+1];
        float rz = sh_rhat[row*3+2];
        const float4* Vp = (const float4*)(V + (size_t)a * 384);
        float4 v0 = __ldg(Vp + lane);
        float4 v1 = __ldg(Vp + 32 + lane);
        float4 v2 = __ldg(Vp + 64 + lane);
        float n0 = sqrtf(v0.x*v0.x + v1.x*v1.x + v2.x*v2.x + 1e-8f);
        float n1 = sqrtf(v0.y*v0.y + v1.y*v1.y + v2.y*v2.y + 1e-8f);
        float n2 = sqrtf(v0.z*v0.z + v1.z*v1.z + v2.z*v2.z + 1e-8f);
        float n3 = sqrtf(v0.w*v0.w + v1.w*v1.w + v2.w*v2.w + 1e-8f);
        float q0 = v0.x*rx + v1.x*ry + v2.x*rz;
        float q1 = v0.y*rx + v1.y*ry + v2.y*rz;
        float q2v= v0.z*rx + v1.z*ry + v2.z*rz;
        float q3 = v0.w*rx + v1.w*ry + v2.w*rz;
        *(__nv_bfloat162*)(bufB + row*136 + lane*4)     = __floats2bfloat162_rn(n0, n1);
        *(__nv_bfloat162*)(bufB + row*136 + lane*4 + 2) = __floats2bfloat162_rn(n2, n3);
        *(__nv_bfloat162*)(bufA + row*136 + lane*4)     = __floats2bfloat162_rn(q0, q1);
        *(__nv_bfloat162*)(bufA + row*136 + lane*4 + 2) = __floats2bfloat162_rn(q2v, q3);
    }
    __syncthreads();   // (5)
    gemm4<8,16,2>(acc, uB, (const uint2*)g_ws1p + 4096 + w*64, lane);
    gemm4<8,16,2>(acc, uA, (const uint2*)g_ws1p + 8192 + w*64, lane);

    // ---- LayerNorm: bias + partials over warp's 16 cols, 8-way combine ----
    float sv[8] = {0,0,0,0,0,0,0,0}, qv[8] = {0,0,0,0,0,0,0,0};  // rows r0+8i
    #pragma unroll
    for (int rb = 0; rb < 4; rb++)
    #pragma unroll
    for (int nt = 0; nt < 2; nt++){
        int c0 = nb + nt*8 + q2;
        float2 bb = *(const float2*)(b_s1 + c0);
        float* a = acc[rb*2+nt];
        a[0]+=bb.x; a[1]+=bb.y; a[2]+=bb.x; a[3]+=bb.y;
        sv[2*rb]   += a[0]+a[1];  qv[2*rb]   += a[0]*a[0]+a[1]*a[1];
        sv[2*rb+1] += a[2]+a[3];  qv[2*rb+1] += a[2]*a[2]+a[3]*a[3];
    }
    #pragma unroll
    for (int o = 1; o < 4; o <<= 1)
    #pragma unroll
    for (int i = 0; i < 8; i++){
        sv[i] += __shfl_xor_sync(0xffffffffu, sv[i], o);
        qv[i] += __shfl_xor_sync(0xffffffffu, qv[i], o);
    }
    if ((lane & 3) == 0){
        #pragma unroll
        for (int i = 0; i < 8; i++){
            int row = r0 + ((i&1)*8) + (i>>1)*16;
            sh_lnp[w*64 + row] = make_float2(sv[i], qv[i]);
        }
    }
    __syncthreads();   // (6)
    #pragma unroll
    for (int rb = 0; rb < 4; rb++){
        float mu[2], rs[2];
        #pragma unroll
        for (int h = 0; h < 2; h++){
            int row = r0 + rb*16 + h*8;
            float ss = 0.f, qq = 0.f;
            #pragma unroll
            for (int ww = 0; ww < 8; ww++){
                float2 p = sh_lnp[ww*64 + row];
                ss += p.x; qq += p.y;
            }
            mu[h] = ss*(1.f/128.f);
            rs[h] = rsqrtf(qq*(1.f/128.f) - mu[h]*mu[h] + 1e-5f);
        }
        #pragma unroll
        for (int nt = 0; nt < 2; nt++){
            int c0 = nb + nt*8 + q2;
            float2 gg = *(const float2*)(g_ln + c0);
            float2 bl = *(const float2*)(b_ln + c0);
            float* a = acc[rb*2+nt];
            float v0 = silu_f((a[0]-mu[0])*rs[0]*gg.x + bl.x);
            float v1 = silu_f((a[1]-mu[0])*rs[0]*gg.y + bl.y);
            float v2 = silu_f((a[2]-mu[1])*rs[1]*gg.x + bl.x);
            float v3 = silu_f((a[3]-mu[1])*rs[1]*gg.y + bl.y);
            *(__nv_bfloat162*)(bufA + (r0+rb*16)*136 + c0)   = __floats2bfloat162_rn(v0, v1);
            *(__nv_bfloat162*)(bufA + (r0+rb*16+8)*136 + c0) = __floats2bfloat162_rn(v2, v3);
        }
    }
    __syncthreads();   // (7)

    // ---- state L2 + fuse z = W*state -> bufB ----
    #pragma unroll
    for (int i = 0; i < 8; i++){ acc[i][0]=acc[i][1]=acc[i][2]=acc[i][3]=0.f; }
    gemm4<8,16,2>(acc, uA, (const uint2*)g_ws2p + w*64, lane);
    #pragma unroll
    for (int rb = 0; rb < 4; rb++)
    #pragma unroll
    for (int nt = 0; nt < 2; nt++){
        int c0 = nb + nt*8 + q2;
        float2 bb  = *(const float2*)(b_s2 + c0);
        float2 wlo = __bfloat1622float2(*(__nv_bfloat162*)(bufW + (r0+rb*16)*136 + c0));
        float2 whi = __bfloat1622float2(*(__nv_bfloat162*)(bufW + (r0+rb*16+8)*136 + c0));
        float* a = acc[rb*2+nt];
        *(__nv_bfloat162*)(bufB + (r0+rb*16)*136 + c0) =
            __floats2bfloat162_rn((a[0]+bb.x)*wlo.x, (a[1]+bb.y)*wlo.y);
        *(__nv_bfloat162*)(bufB + (r0+rb*16+8)*136 + c0) =
            __floats2bfloat162_rn((a[2]+bb.x)*whi.x, (a[3]+bb.y)*whi.y);
    }
    __syncthreads();   // (8)

    // ---- output head: z @ w_o1 (warp covers 8 of 64 cols, NTU=1) ----
    #pragma unroll
    for (int i = 0; i < 4; i++){ acc[i][0]=acc[i][1]=acc[i][2]=acc[i][3]=0.f; }
    gemm4<8,8,1>(acc, uB, (const uint2*)g_wo1p + w*32, lane);
    float m[8] = {0,0,0,0,0,0,0,0};
    #pragma unroll
    for (int rb = 0; rb < 4; rb++){
        int c0 = w*8 + q2;
        float2 bb = *(const float2*)(b_o1 + c0);
        float2 w2 = *(const float2*)(w_o2 + c0);
        float* a = acc[rb];
        m[2*rb]   += silu_f(a[0]+bb.x)*w2.x + silu_f(a[1]+bb.y)*w2.y;
        m[2*rb+1] += silu_f(a[2]+bb.x)*w2.x + silu_f(a[3]+bb.y)*w2.y;
    }
    #pragma unroll
    for (int i = 0; i < 8; i++){
        m[i] += __shfl_xor_sync(0xffffffffu, m[i], 1);
        m[i] += __shfl_xor_sync(0xffffffffu, m[i], 2);
    }
    if ((lane & 3) == 0){
        #pragma unroll
        for (int i = 0; i < 8; i++){
            int row = r0 + ((i&1)*8) + (i>>1)*16;
            sh_m[w*64 + row] = m[i];
        }
    }
    __syncthreads();   // (9)
    if (tid < MTILE){
        int e = e0 + tid;
        if (e < E){
            float ms = b_o2[0];
            #pragma unroll
            for (int ww = 0; ww < 8; ww++) ms += sh_m[ww*64 + tid];
            atomicAdd(rho + sh_pidx[tid], ms * sh_env[tid]);
        }
    }
}

extern "C" void kernel_launch(void* const* d_in, const int* in_sizes, int n_in,
                              void* d_out, int out_size)
{
    const float* diff = (const float*)d_in[0];
    const float* S    = (const float*)d_in[1];
    const float* V    = (const float*)d_in[2];
    const int*   aidx = (const int*)d_in[3];
    const int*   pidx = (const int*)d_in[4];

    int base = 5;
    if (n_in > 5 && in_sizes[5] == 1) base = 6;

    const float* w_s1 = (const float*)d_in[base + 0];
    const float* b_s1 = (const float*)d_in[base + 1];
    const float* g_ln = (const float*)d_in[base + 2];
    const float* b_ln = (const float*)d_in[base + 3];
    const float* w_s2 = (const float*)d_in[base + 4];
    const float* b_s2 = (const float*)d_in[base + 5];
    const float* w_f1 = (const float*)d_in[base + 6];
    const float* b_f1 = (const float*)d_in[base + 7];
    const float* w_f2 = (const float*)d_in[base + 8];
    const float* b_f2 = (const float*)d_in[base + 9];
    const float* w_o1 = (const float*)d_in[base + 10];
    const float* b_o1 = (const float*)d_in[base + 11];
    const float* w_o2 = (const float*)d_in[base + 12];
    const float* b_o2 = (const float*)d_in[base + 13];
    const float* fb   = (const float*)d_in[base + 14];

    int E = in_sizes[0] / 3;
    float* rho = (float*)d_out;

    int prep_threads = 736*32 + out_size;
    prep_kernel<<<(prep_threads + 255)/256, 256>>>(w_s1, w_s2, w_f1, w_f2, w_o1,
                                                   rho, fb, out_size);

    cudaFuncSetAttribute(cfr_mma_kernel, cudaFuncAttributeMaxDynamicSharedMemorySize, SMEM_BYTES);
    cudaFuncSetAttribute(cfr_mma_kernel, cudaFuncAttributePreferredSharedMemoryCarveout, 100);
    cfr_mma_kernel<<<(E + MTILE - 1)/MTILE, THREADS, SMEM_BYTES>>>(
        diff, S, V, aidx, pidx,
        b_s1, g_ln, b_ln, b_s2, b_f1, b_f2,
        b_o1, w_o2, b_o2, rho, E);
}